// round 1
// baseline (speedup 1.0000x reference)
#include <cuda_runtime.h>

#define NN 50000
#define EE 800000
#define INF 128
#define HD  128
#define NEG 0.2f

// ---------------- scratch (static device allocations; no cudaMalloc) ----------
__device__ float g_fsrc[(size_t)NN * HD];
__device__ float g_fdst[(size_t)NN * HD];
__device__ float g_fv  [(size_t)NN * HD];
__device__ int   g_deg [NN];
__device__ int   g_offs[NN + 1];
__device__ int   g_cur [NN];
__device__ int   g_ssrc[EE];

// ---------------- fused projection GEMM: out[n][j] = feat[n,:] . W[j,:] + b[j]
// BM=64 nodes, BN=128 outputs, K split into 2 chunks of 64. 256 threads,
// thread tile = 4 nodes x 8 j. W held transposed in smem for conflict-free LDS.
__global__ void gemm_kernel(const float* __restrict__ feat,
                            const float* __restrict__ Wsrc, const float* __restrict__ bsrc,
                            const float* __restrict__ Wdst, const float* __restrict__ bdst,
                            const float* __restrict__ Wv,   const float* __restrict__ bv)
{
    __shared__ float As[64 * 64];    // [node][k]  16 KB
    __shared__ float Wt[64 * 128];   // [k][j]     32 KB

    const float* W;
    const float* b;
    float* Out;
    if (blockIdx.y == 0)      { W = Wsrc; b = bsrc; Out = g_fsrc; }
    else if (blockIdx.y == 1) { W = Wdst; b = bdst; Out = g_fdst; }
    else                      { W = Wv;   b = bv;   Out = g_fv;   }

    const int tid = threadIdx.x;
    const int jg  = tid & 15;     // j base = jg*8
    const int ng  = tid >> 4;     // node base = ng*4
    const int n0  = blockIdx.x * 64;

    float acc[4][8];
#pragma unroll
    for (int i = 0; i < 4; i++)
#pragma unroll
        for (int j = 0; j < 8; j++) acc[i][j] = 0.f;

    for (int kc = 0; kc < 2; kc++) {
        const int k0 = kc * 64;
        // load A tile: 64 rows x 16 float4
#pragma unroll
        for (int t = tid; t < 1024; t += 256) {
            int r = t >> 4, c = t & 15;
            int n = n0 + r;
            float4 v = make_float4(0.f, 0.f, 0.f, 0.f);
            if (n < NN) v = *(const float4*)(feat + (size_t)n * INF + k0 + c * 4);
            *(float4*)(As + r * 64 + c * 4) = v;
        }
        // load W chunk transposed: Wt[kk][j] = W[j][k0+kk]
#pragma unroll
        for (int t = tid; t < 8192; t += 256) {
            int j = t >> 6, kk = t & 63;
            Wt[kk * 128 + j] = W[j * INF + k0 + kk];
        }
        __syncthreads();

#pragma unroll 16
        for (int kk = 0; kk < 64; kk++) {
            float av[4];
#pragma unroll
            for (int i = 0; i < 4; i++) av[i] = As[(ng * 4 + i) * 64 + kk];
            const float4 w0 = *(const float4*)(Wt + kk * 128 + jg * 8);
            const float4 w1 = *(const float4*)(Wt + kk * 128 + jg * 8 + 4);
            const float wv[8] = {w0.x, w0.y, w0.z, w0.w, w1.x, w1.y, w1.z, w1.w};
#pragma unroll
            for (int i = 0; i < 4; i++)
#pragma unroll
                for (int j = 0; j < 8; j++) acc[i][j] += av[i] * wv[j];
        }
        __syncthreads();
    }

#pragma unroll
    for (int i = 0; i < 4; i++) {
        int n = n0 + ng * 4 + i;
        if (n >= NN) continue;
#pragma unroll
        for (int j0 = 0; j0 < 8; j0 += 4) {
            float4 o;
            o.x = acc[i][j0 + 0] + b[jg * 8 + j0 + 0];
            o.y = acc[i][j0 + 1] + b[jg * 8 + j0 + 1];
            o.z = acc[i][j0 + 2] + b[jg * 8 + j0 + 2];
            o.w = acc[i][j0 + 3] + b[jg * 8 + j0 + 3];
            *(float4*)(Out + (size_t)n * HD + jg * 8 + j0) = o;
        }
    }
}

// ---------------- CSR build ---------------------------------------------------
__global__ void zero_deg_kernel()
{
    int i = blockIdx.x * blockDim.x + threadIdx.x;
    if (i < NN) g_deg[i] = 0;
}

__global__ void hist_kernel(const int* __restrict__ dst)
{
    int i = blockIdx.x * blockDim.x + threadIdx.x;
    if (i < EE) atomicAdd(&g_deg[dst[i]], 1);
}

// single-block exclusive scan over NN degrees -> offsets + cursors
__global__ void scan_kernel()
{
    __shared__ int sums[1024];
    const int tid = threadIdx.x;
    const int CH  = (NN + 1023) / 1024;   // 49
    const int base = tid * CH;

    int s = 0;
    for (int i = 0; i < CH; i++) {
        int idx = base + i;
        if (idx < NN) s += g_deg[idx];
    }
    sums[tid] = s;
    __syncthreads();
    for (int off = 1; off < 1024; off <<= 1) {
        int v = (tid >= off) ? sums[tid - off] : 0;
        __syncthreads();
        sums[tid] += v;
        __syncthreads();
    }
    int run = (tid == 0) ? 0 : sums[tid - 1];
    for (int i = 0; i < CH; i++) {
        int idx = base + i;
        if (idx < NN) {
            g_offs[idx] = run;
            g_cur[idx]  = run;
            run += g_deg[idx];
        }
    }
    if (tid == 1023) g_offs[NN] = sums[1023];
}

__global__ void scatter_kernel(const int* __restrict__ src, const int* __restrict__ dst)
{
    int i = blockIdx.x * blockDim.x + threadIdx.x;
    if (i < EE) {
        int d = dst[i];
        int p = atomicAdd(&g_cur[d], 1);
        g_ssrc[p] = src[i];
    }
}

// ---------------- aggregation: one warp per dst node --------------------------
// num[n,:] = sum_e fv[src_e,:] * exp(lrelu(fs[src_e,:] + fd[n,:]))
// den[n,:] = sum_e              exp(lrelu(fs[src_e,:] + fd[n,:]))
// out = num / den   (softmax max-shift skipped: logits bounded, ratio identical)
__global__ void aggregate_kernel(float* __restrict__ out)
{
    const int warp = (blockIdx.x * blockDim.x + threadIdx.x) >> 5;
    if (warp >= NN) return;
    const int lane = threadIdx.x & 31;
    const int n = warp;

    const int beg = g_offs[n];
    const int end = g_offs[n + 1];

    const size_t fo = (size_t)n * HD + lane * 4;
    const float4 fd = *(const float4*)(g_fdst + fo);

    float nx = 0.f, ny = 0.f, nz = 0.f, nw = 0.f;
    float dx = 0.f, dy = 0.f, dz = 0.f, dw = 0.f;

    for (int base = beg; base < end; base += 32) {
        const int rem = end - base;
        const int s_l = (lane < rem) ? g_ssrc[base + lane] : 0;
        const int m = rem < 32 ? rem : 32;
#pragma unroll 4
        for (int t = 0; t < m; t++) {
            const int s = __shfl_sync(0xffffffffu, s_l, t);
            const size_t so = (size_t)s * HD + lane * 4;
            const float4 fs  = *(const float4*)(g_fsrc + so);
            const float4 fvv = *(const float4*)(g_fv + so);
            float a, e;
            a = fs.x + fd.x; e = __expf(a >= 0.f ? a : NEG * a); dx += e; nx += fvv.x * e;
            a = fs.y + fd.y; e = __expf(a >= 0.f ? a : NEG * a); dy += e; ny += fvv.y * e;
            a = fs.z + fd.z; e = __expf(a >= 0.f ? a : NEG * a); dz += e; nz += fvv.z * e;
            a = fs.w + fd.w; e = __expf(a >= 0.f ? a : NEG * a); dw += e; nw += fvv.w * e;
        }
    }

    float4 o;
    o.x = dx > 0.f ? nx / dx : 0.f;
    o.y = dy > 0.f ? ny / dy : 0.f;
    o.z = dz > 0.f ? nz / dz : 0.f;
    o.w = dw > 0.f ? nw / dw : 0.f;
    *(float4*)(out + fo) = o;
}

// ---------------- launch -------------------------------------------------------
extern "C" void kernel_launch(void* const* d_in, const int* in_sizes, int n_in,
                              void* d_out, int out_size)
{
    const float* feat = (const float*)d_in[0];
    const float* Wsrc = (const float*)d_in[1];
    const float* bsrc = (const float*)d_in[2];
    const float* Wdst = (const float*)d_in[3];
    const float* bdst = (const float*)d_in[4];
    const float* Wv   = (const float*)d_in[5];
    const float* bv   = (const float*)d_in[6];
    const int*   src  = (const int*)d_in[7];
    const int*   dst  = (const int*)d_in[8];
    float* out = (float*)d_out;

    dim3 gg((NN + 63) / 64, 3);
    gemm_kernel<<<gg, 256>>>(feat, Wsrc, bsrc, Wdst, bdst, Wv, bv);

    zero_deg_kernel<<<(NN + 255) / 256, 256>>>();
    hist_kernel<<<(EE + 255) / 256, 256>>>(dst);
    scan_kernel<<<1, 1024>>>();
    scatter_kernel<<<(EE + 255) / 256, 256>>>(src, dst);

    aggregate_kernel<<<(NN * 32 + 255) / 256, 256>>>(out);
}

// round 2
// speedup vs baseline: 1.6491x; 1.6491x over previous
#include <cuda_runtime.h>

#define NN 50000
#define EE 800000
#define INF 128
#define HD  128
#define NEG 0.2f

#define BM 128
#define BK 32
#define NTILE ((NN + BM - 1) / BM)    // 391
#define HBLK 148
#define ASP 130                        // pair stride per k-row (pad vs bank conflicts)
#define WTS 132                        // float stride per k-row
#define SMEM_BYTES ((BK * ASP * 2 + BK * WTS) * 4)

// ---------------- scratch ------------------------------------------------------
__device__ float g_fsrc[(size_t)NN * HD];
__device__ float g_fdst[(size_t)NN * HD];
__device__ float g_fv  [(size_t)NN * HD];
__device__ int   g_deg [NN];          // zero-initialized; re-zeroed by scan_kernel
__device__ int   g_offs[NN + 1];
__device__ int   g_cur [NN];
__device__ int   g_ssrc[EE];

#define FFMA2(d, a, b) asm("fma.rn.f32x2 %0, %1, %2, %0;" : "+l"(d) : "l"(a), "l"(b))

// ---------------- fused projection GEMM (f32x2) + dst histogram ----------------
// out[n][j] = feat[n,:] . W[j,:] + b[j].  Blocks < HBLK build the degree
// histogram (memory-light, overlaps the FMA-bound GEMM blocks).
// GEMM: BMxBN=128x128 tile, BK=32, 256 threads, micro-tile 16m x 4n.
// Accumulators paired over n (FFMA2); a replicated {a,a} in smem (warp-broadcast
// reads -> conflict-free), w read as natural consecutive pairs (LDS.128,
// 16B-stride across lanes -> conflict-free).
__global__ void __launch_bounds__(256, 2)
gemm_hist_kernel(const float* __restrict__ feat,
                 const float* __restrict__ Wsrc, const float* __restrict__ bsrc,
                 const float* __restrict__ Wdst, const float* __restrict__ bdst,
                 const float* __restrict__ Wv,   const float* __restrict__ bv,
                 const int* __restrict__ dst)
{
    if (blockIdx.x < HBLK) {
        for (int i = blockIdx.x * 256 + threadIdx.x; i < EE; i += HBLK * 256)
            atomicAdd(&g_deg[dst[i]], 1);
        return;
    }

    extern __shared__ float sm[];
    float* As2 = sm;                    // BK rows of ASP pairs ({a,a} float2)
    float* Wt  = sm + BK * ASP * 2;     // BK rows of WTS floats

    const int bx   = blockIdx.x - HBLK;
    const int mat  = bx / NTILE;
    const int tile = bx % NTILE;

    const float* W;
    const float* b;
    float* Out;
    if (mat == 0)      { W = Wsrc; b = bsrc; Out = g_fsrc; }
    else if (mat == 1) { W = Wdst; b = bdst; Out = g_fdst; }
    else               { W = Wv;   b = bv;   Out = g_fv;   }

    const int tid = threadIdx.x;
    const int tx  = tid & 31;     // n0 = tx*4
    const int ty  = tid >> 5;     // m0 = ty*16
    const int m0g = tile * BM;

    unsigned long long acc[16][2];
#pragma unroll
    for (int m = 0; m < 16; m++) { acc[m][0] = 0ULL; acc[m][1] = 0ULL; }

    for (int kc = 0; kc < INF / BK; kc++) {
        const int k0 = kc * BK;

        // feat tile -> As2[kk][m] replicated pairs
#pragma unroll
        for (int t = tid; t < BM * BK / 4; t += 256) {
            const int r = t >> 3, c = t & 7;
            const int row = m0g + r;
            float4 v = make_float4(0.f, 0.f, 0.f, 0.f);
            if (row < NN) v = *(const float4*)(feat + (size_t)row * INF + k0 + c * 4);
            float* p;
            p = As2 + ((c * 4 + 0) * ASP + r) * 2; p[0] = v.x; p[1] = v.x;
            p = As2 + ((c * 4 + 1) * ASP + r) * 2; p[0] = v.y; p[1] = v.y;
            p = As2 + ((c * 4 + 2) * ASP + r) * 2; p[0] = v.z; p[1] = v.z;
            p = As2 + ((c * 4 + 3) * ASP + r) * 2; p[0] = v.w; p[1] = v.w;
        }
        // W tile -> Wt[kk][j]
#pragma unroll
        for (int t = tid; t < HD * BK / 4; t += 256) {
            const int j = t >> 3, c = t & 7;
            const float4 w4 = *(const float4*)(W + (size_t)j * INF + k0 + c * 4);
            Wt[(c * 4 + 0) * WTS + j] = w4.x;
            Wt[(c * 4 + 1) * WTS + j] = w4.y;
            Wt[(c * 4 + 2) * WTS + j] = w4.z;
            Wt[(c * 4 + 3) * WTS + j] = w4.w;
        }
        __syncthreads();

#pragma unroll 16
        for (int kk = 0; kk < BK; kk++) {
            const ulonglong2 wv = *(const ulonglong2*)(Wt + kk * WTS + tx * 4);
            const float* abase = As2 + (kk * ASP + ty * 16) * 2;
#pragma unroll
            for (int j = 0; j < 8; j++) {
                const ulonglong2 av = *(const ulonglong2*)(abase + j * 4);
                FFMA2(acc[2 * j + 0][0], av.x, wv.x);
                FFMA2(acc[2 * j + 0][1], av.x, wv.y);
                FFMA2(acc[2 * j + 1][0], av.y, wv.x);
                FFMA2(acc[2 * j + 1][1], av.y, wv.y);
            }
        }
        __syncthreads();
    }

    const float4 bb = *(const float4*)(b + tx * 4);
#pragma unroll
    for (int m = 0; m < 16; m++) {
        const int row = m0g + ty * 16 + m;
        if (row < NN) {
            const float2 lo = *(const float2*)&acc[m][0];
            const float2 hi = *(const float2*)&acc[m][1];
            float4 o;
            o.x = lo.x + bb.x; o.y = lo.y + bb.y;
            o.z = hi.x + bb.z; o.w = hi.y + bb.w;
            *(float4*)(Out + (size_t)row * HD + tx * 4) = o;
        }
    }
}

// ---------------- scan: coalesced tiled block scan; re-zeroes g_deg -----------
__global__ void scan_kernel()
{
    __shared__ int wsums[32];
    const int tid  = threadIdx.x;
    const int lane = tid & 31;
    const int wid  = tid >> 5;
    const int TILES = (NN + 1023) / 1024;

    int carry = 0;
    for (int t = 0; t < TILES; t++) {
        const int idx = t * 1024 + tid;
        int v = 0;
        if (idx < NN) { v = g_deg[idx]; g_deg[idx] = 0; }
        int s = v;
#pragma unroll
        for (int o = 1; o < 32; o <<= 1) {
            const int u = __shfl_up_sync(0xffffffffu, s, o);
            if (lane >= o) s += u;
        }
        if (lane == 31) wsums[wid] = s;
        __syncthreads();
        if (wid == 0) {
            int ws = wsums[lane];
#pragma unroll
            for (int o = 1; o < 32; o <<= 1) {
                const int u = __shfl_up_sync(0xffffffffu, ws, o);
                if (lane >= o) ws += u;
            }
            wsums[lane] = ws;
        }
        __syncthreads();
        const int excl = carry + (s - v) + (wid ? wsums[wid - 1] : 0);
        if (idx < NN) { g_offs[idx] = excl; g_cur[idx] = excl; }
        carry += wsums[31];
        __syncthreads();
    }
    if (tid == 0) g_offs[NN] = carry;
}

// ---------------- scatter ------------------------------------------------------
__global__ void scatter_kernel(const int* __restrict__ src, const int* __restrict__ dst)
{
    const int i = blockIdx.x * blockDim.x + threadIdx.x;
    if (i < EE) {
        const int d = dst[i];
        const int p = atomicAdd(&g_cur[d], 1);
        g_ssrc[p] = src[i];
    }
}

// ---------------- aggregation: one warp per dst node --------------------------
__global__ void aggregate_kernel(float* __restrict__ out)
{
    const int warp = (blockIdx.x * blockDim.x + threadIdx.x) >> 5;
    if (warp >= NN) return;
    const int lane = threadIdx.x & 31;
    const int n = warp;

    const int beg = g_offs[n];
    const int end = g_offs[n + 1];

    const size_t fo = (size_t)n * HD + lane * 4;
    const float4 fd = *(const float4*)(g_fdst + fo);

    float nx = 0.f, ny = 0.f, nz = 0.f, nw = 0.f;
    float dx = 0.f, dy = 0.f, dz = 0.f, dw = 0.f;

    for (int base = beg; base < end; base += 32) {
        const int rem = end - base;
        const int s_l = (lane < rem) ? g_ssrc[base + lane] : 0;
        const int m = rem < 32 ? rem : 32;
#pragma unroll 4
        for (int t = 0; t < m; t++) {
            const int s = __shfl_sync(0xffffffffu, s_l, t);
            const size_t so = (size_t)s * HD + lane * 4;
            const float4 fs  = *(const float4*)(g_fsrc + so);
            const float4 fvv = *(const float4*)(g_fv + so);
            float a, e;
            a = fs.x + fd.x; e = __expf(a >= 0.f ? a : NEG * a); dx += e; nx += fvv.x * e;
            a = fs.y + fd.y; e = __expf(a >= 0.f ? a : NEG * a); dy += e; ny += fvv.y * e;
            a = fs.z + fd.z; e = __expf(a >= 0.f ? a : NEG * a); dz += e; nz += fvv.z * e;
            a = fs.w + fd.w; e = __expf(a >= 0.f ? a : NEG * a); dw += e; nw += fvv.w * e;
        }
    }

    float4 o;
    o.x = dx > 0.f ? nx / dx : 0.f;
    o.y = dy > 0.f ? ny / dy : 0.f;
    o.z = dz > 0.f ? nz / dz : 0.f;
    o.w = dw > 0.f ? nw / dw : 0.f;
    *(float4*)(out + fo) = o;
}

// ---------------- launch -------------------------------------------------------
extern "C" void kernel_launch(void* const* d_in, const int* in_sizes, int n_in,
                              void* d_out, int out_size)
{
    const float* feat = (const float*)d_in[0];
    const float* Wsrc = (const float*)d_in[1];
    const float* bsrc = (const float*)d_in[2];
    const float* Wdst = (const float*)d_in[3];
    const float* bdst = (const float*)d_in[4];
    const float* Wv   = (const float*)d_in[5];
    const float* bv   = (const float*)d_in[6];
    const int*   src  = (const int*)d_in[7];
    const int*   dst  = (const int*)d_in[8];
    float* out = (float*)d_out;

    cudaFuncSetAttribute(gemm_hist_kernel,
                         cudaFuncAttributeMaxDynamicSharedMemorySize, SMEM_BYTES);

    gemm_hist_kernel<<<HBLK + 3 * NTILE, 256, SMEM_BYTES>>>(
        feat, Wsrc, bsrc, Wdst, bdst, Wv, bv, dst);

    scan_kernel<<<1, 1024>>>();
    scatter_kernel<<<(EE + 255) / 256, 256>>>(src, dst);
    aggregate_kernel<<<(NN * 32 + 255) / 256, 256>>>(out);
}